// round 16
// baseline (speedup 1.0000x reference)
#include <cuda_runtime.h>
#include <cuda_bf16.h>
#include <math.h>

typedef unsigned long long u64;

// Problem constants (fixed by the dataset)
#define BB 2
#define HH 12
#define SS 3456
#define DD 32
#define FPT 216           // feats per timestep
#define NT (SS / FPT)     // 16 timesteps
#define WIN 8
#define IMG_START 20      // FPT - img_feat_size(196)
#define JOINT_START 4     // IMG_START - act_size(16)
#define NPAST 19          // valid past kv_m: {0,1,2,3,5..19}
#define MAXPAST ((WIN - 1) * NPAST)   // 133
#define NIMG (FPT - IMG_START)        // 196

// scale * log2(e): ex2.approx(dot) == exp(dot/sqrt(32))
#define SCL2E (0.17677669529663689f * 1.4426950408889634f)

__device__ __forceinline__ u64 fma2(u64 a, u64 b, u64 c) {
    u64 d; asm("fma.rn.f32x2 %0, %1, %2, %3;" : "=l"(d) : "l"(a), "l"(b), "l"(c)); return d;
}
__device__ __forceinline__ u64 pack2(float lo, float hi) {
    u64 d; asm("mov.b64 %0, {%1, %2};" : "=l"(d) : "f"(lo), "f"(hi)); return d;
}
__device__ __forceinline__ void unpack2(u64 a, float& lo, float& hi) {
    asm("mov.b64 {%0, %1}, %2;" : "=f"(lo), "=f"(hi) : "l"(a));
}
__device__ __forceinline__ float ex2(float x) {
    float r; asm("ex2.approx.f32 %0, %1;" : "=f"(r) : "f"(x)); return r;
}

// one key step: dot(q,k) via f32x2, exp, accumulate p*v (rows via generic ptrs)
__device__ __forceinline__ void keyStep(const u64* __restrict__ q2, u64* __restrict__ acc,
                                        float& lsum, const float* krow, const float* vrow)
{
    const ulonglong2* k2 = (const ulonglong2*)krow;
    u64 sA = 0ull, sB = 0ull, sC = 0ull, sD = 0ull;
    ulonglong2 kk;
    kk = k2[0]; sA = fma2(q2[0],  kk.x, sA); sB = fma2(q2[1],  kk.y, sB);
    kk = k2[1]; sC = fma2(q2[2],  kk.x, sC); sD = fma2(q2[3],  kk.y, sD);
    kk = k2[2]; sA = fma2(q2[4],  kk.x, sA); sB = fma2(q2[5],  kk.y, sB);
    kk = k2[3]; sC = fma2(q2[6],  kk.x, sC); sD = fma2(q2[7],  kk.y, sD);
    kk = k2[4]; sA = fma2(q2[8],  kk.x, sA); sB = fma2(q2[9],  kk.y, sB);
    kk = k2[5]; sC = fma2(q2[10], kk.x, sC); sD = fma2(q2[11], kk.y, sD);
    kk = k2[6]; sA = fma2(q2[12], kk.x, sA); sB = fma2(q2[13], kk.y, sB);
    kk = k2[7]; sC = fma2(q2[14], kk.x, sC); sD = fma2(q2[15], kk.y, sD);
    const u64 one2 = pack2(1.0f, 1.0f);
    u64 sAB = fma2(sA, one2, sB);
    u64 sCD = fma2(sC, one2, sD);
    u64 sT  = fma2(sAB, one2, sCD);
    float lo, hi; unpack2(sT, lo, hi);
    const float p = ex2(lo + hi);
    lsum += p;
    const u64 p2 = pack2(p, p);
    const ulonglong2* v2 = (const ulonglong2*)vrow;
    ulonglong2 vv;
    vv = v2[0]; acc[0]  = fma2(p2, vv.x, acc[0]);  acc[1]  = fma2(p2, vv.y, acc[1]);
    vv = v2[1]; acc[2]  = fma2(p2, vv.x, acc[2]);  acc[3]  = fma2(p2, vv.y, acc[3]);
    vv = v2[2]; acc[4]  = fma2(p2, vv.x, acc[4]);  acc[5]  = fma2(p2, vv.y, acc[5]);
    vv = v2[3]; acc[6]  = fma2(p2, vv.x, acc[6]);  acc[7]  = fma2(p2, vv.y, acc[7]);
    vv = v2[4]; acc[8]  = fma2(p2, vv.x, acc[8]);  acc[9]  = fma2(p2, vv.y, acc[9]);
    vv = v2[5]; acc[10] = fma2(p2, vv.x, acc[10]); acc[11] = fma2(p2, vv.y, acc[11]);
    vv = v2[6]; acc[12] = fma2(p2, vv.x, acc[12]); acc[13] = fma2(p2, vv.y, acc[13]);
    vv = v2[7]; acc[14] = fma2(p2, vv.x, acc[14]); acc[15] = fma2(p2, vv.y, acc[15]);
}

__device__ __forceinline__ void loadQ(const float* qrowp, u64* q2)
{
    const float4* qg4 = (const float4*)qrowp;
    #pragma unroll
    for (int i = 0; i < 8; i++) {
        float4 x = qg4[i];
        q2[2 * i]     = pack2(x.x * SCL2E, x.y * SCL2E);
        q2[2 * i + 1] = pack2(x.z * SCL2E, x.w * SCL2E);
    }
}

// ============================================================================
// SINGLE kernel.  256 threads, 8 warps, 39KB tile + 5.8KB partials,
// 3 blocks/SM, one launch.
//  tid   0..195 : img query 20+tid over shared tile (20 same-t + npk past) -> out
//  tid 196..215 : head query tid-196 over shared tile (20 + n4/npk) -> partial[0]
//  tid 216..223 : idle (warp 6 tail)
//  tid 224..255 : warp 7, lane<20 = head query lane; 196 same-t IMG keys
//                 read from GLOBAL with warp-uniform (broadcast) addresses
//                 (valid for ALL head queries, no masking) -> partial[1]
//  combine: 160 threads sum partial[0]+partial[1], normalize, write head rows.
// ============================================================================
#define THREADS 256
#define SK20 0
#define SV20 (IMG_START * DD)                       // 640
#define PKO  (2 * IMG_START * DD)                   // 1280
#define PVO  (2 * IMG_START * DD + MAXPAST * DD)    // 5536
#define TILE_FLOATS (2 * IMG_START * DD + 2 * MAXPAST * DD)  // 9792
#define PSTRIDE 36
#define SMEM_BYTES ((TILE_FLOATS + 2 * 20 * PSTRIDE) * 4)    // 44928

__global__ void __launch_bounds__(THREADS, 3)
eye_attn(const float* __restrict__ q,
         const float* __restrict__ k,
         const float* __restrict__ v,
         float* __restrict__ out)
{
    extern __shared__ float smem[];
    float* sK20 = smem + SK20;
    float* sV20 = smem + SV20;
    float* pK   = smem + PKO;
    float* pV   = smem + PVO;
    float* part = smem + TILE_FLOATS;   // [2][20][PSTRIDE]

    const int t = blockIdx.x, h = blockIdx.y, b = blockIdx.z;
    const int tid = threadIdx.x;
    const size_t bh_base = ((size_t)(b * HH + h)) * SS * DD;
    const float* kg = k + bh_base + (size_t)t * FPT * DD;
    const float* vg = v + bh_base + (size_t)t * FPT * DD;

    // stage same-t rows 0..19 (160 float4 each)
    {
        const float4* kg4 = (const float4*)kg;
        const float4* vg4 = (const float4*)vg;
        for (int i = tid; i < IMG_START * DD / 4; i += THREADS) {
            ((float4*)sK20)[i] = kg4[i];
            ((float4*)sV20)[i] = vg4[i];
        }
    }

    const int npt = (t < WIN - 1) ? t : (WIN - 1);
    const int npk = npt * NPAST;
    const int n4  = npt * 4;

    // stage compacted past rows, JOINT-FIRST order:
    // rows [0, n4)   : m in {0,1,2,3}  (visible to all queries)
    // rows [n4, npk) : m in {5..19}    (invisible to joint queries 4..19)
    {
        const int ntask = npk * 8;
        for (int r4 = tid; r4 < ntask; r4 += THREADS) {
            const int r = r4 >> 3, c = r4 & 7;
            int dt, m;
            if (r < n4) { dt = (r >> 2) + 1; m = r & 3; }
            else        { const int r2 = r - n4; dt = r2 / 15 + 1; m = 5 + r2 - (dt - 1) * 15; }
            const size_t src = bh_base + ((size_t)(t - dt) * FPT + m) * DD;
            ((float4*)pK)[r * 8 + c] = ((const float4*)(k + src))[c];
            ((float4*)pV)[r * 8 + c] = ((const float4*)(v + src))[c];
        }
    }

    __syncthreads();

    if (tid < NIMG + IMG_START) {
        // ---------- shared-tile paths (img queries + head partials) ----------
        const bool isImg = (tid < NIMG);
        const int qrow = isImg ? (IMG_START + tid) : (tid - NIMG);
        const bool joint = !isImg && (qrow >= JOINT_START);
        const int nk = IMG_START + (joint ? n4 : npk);

        u64 q2[16];
        loadQ(q + bh_base + ((size_t)t * FPT + qrow) * DD, q2);

        u64 acc[16];
        #pragma unroll
        for (int i = 0; i < 16; i++) acc[i] = 0ull;
        float lsum = 0.0f;

        const float* pKb = pK - IMG_START * DD;
        const float* pVb = pV - IMG_START * DD;
        #pragma unroll 2
        for (int idx = 0; idx < nk; idx++) {
            const float* kr = ((idx < IMG_START) ? sK20 : pKb) + idx * DD;
            const float* vr = ((idx < IMG_START) ? sV20 : pVb) + idx * DD;
            keyStep(q2, acc, lsum, kr, vr);
        }

        if (isImg) {
            const float inv = 1.0f / lsum;
            float4* og4 = (float4*)(out + bh_base + ((size_t)t * FPT + qrow) * DD);
            #pragma unroll
            for (int i = 0; i < 8; i++) {
                float a0, a1, a2, a3;
                unpack2(acc[2 * i], a0, a1);
                unpack2(acc[2 * i + 1], a2, a3);
                float4 o; o.x = a0 * inv; o.y = a1 * inv; o.z = a2 * inv; o.w = a3 * inv;
                og4[i] = o;
            }
        } else {
            float* pp = part + (0 * 20 + qrow) * PSTRIDE;
            #pragma unroll
            for (int i = 0; i < 16; i++) {
                float lo, hi; unpack2(acc[i], lo, hi);
                pp[2 * i] = lo; pp[2 * i + 1] = hi;
            }
            pp[32] = lsum;
        }
    } else if (tid >= 224) {
        // ---------- warp 7: head queries x same-t IMG keys, global broadcast ----------
        const int lane = tid - 224;
        const int qi = (lane < 20) ? lane : 19;   // dups discarded

        u64 q2[16];
        loadQ(q + bh_base + ((size_t)t * FPT + qi) * DD, q2);

        u64 acc[16];
        #pragma unroll
        for (int i = 0; i < 16; i++) acc[i] = 0ull;
        float lsum = 0.0f;

        const float* kImg = kg + (size_t)IMG_START * DD;
        const float* vImg = vg + (size_t)IMG_START * DD;
        #pragma unroll 2
        for (int r = 0; r < NIMG; r++)
            keyStep(q2, acc, lsum, kImg + (size_t)r * DD, vImg + (size_t)r * DD);

        if (lane < 20) {
            float* pp = part + (1 * 20 + qi) * PSTRIDE;
            #pragma unroll
            for (int i = 0; i < 16; i++) {
                float lo, hi; unpack2(acc[i], lo, hi);
                pp[2 * i] = lo; pp[2 * i + 1] = hi;
            }
            pp[32] = lsum;
        }
    }

    __syncthreads();

    // combine head-query partials: 160 threads = 20 queries x 8 float4-slots
    if (tid < 160) {
        const int qo = tid >> 3;
        const int c  = tid & 7;
        const float* p0 = part + (0 * 20 + qo) * PSTRIDE;
        const float* p1 = part + (1 * 20 + qo) * PSTRIDE;
        const float lt = p0[32] + p1[32];
        const float inv = 1.0f / lt;
        float4 a = ((const float4*)p0)[c];
        float4 d = ((const float4*)p1)[c];
        float4 o;
        o.x = (a.x + d.x) * inv; o.y = (a.y + d.y) * inv;
        o.z = (a.z + d.z) * inv; o.w = (a.w + d.w) * inv;
        ((float4*)(out + bh_base + ((size_t)t * FPT + qo) * DD))[c] = o;
    }
}

extern "C" void kernel_launch(void* const* d_in, const int* in_sizes, int n_in,
                              void* d_out, int out_size)
{
    const float* q = (const float*)d_in[0];
    const float* k = (const float*)d_in[1];
    const float* v = (const float*)d_in[2];
    float* out = (float*)d_out;

    cudaFuncSetAttribute(eye_attn,
                         cudaFuncAttributeMaxDynamicSharedMemorySize, SMEM_BYTES);

    dim3 grid(NT, HH, BB);   // (16, 12, 2)
    eye_attn<<<grid, THREADS, SMEM_BYTES>>>(q, k, v, out);
}

// round 17
// speedup vs baseline: 1.5800x; 1.5800x over previous
#include <cuda_runtime.h>
#include <cuda_bf16.h>
#include <math.h>

typedef unsigned long long u64;

// Problem constants (fixed by the dataset)
#define BB 2
#define HH 12
#define SS 3456
#define DD 32
#define FPT 216           // feats per timestep
#define NT (SS / FPT)     // 16 timesteps
#define WIN 8
#define IMG_START 20      // FPT - img_feat_size(196)
#define JOINT_START 4     // IMG_START - act_size(16)
#define NPAST 19          // valid past kv_m: {0,1,2,3,5..19}
#define MAXPAST ((WIN - 1) * NPAST)   // 133
#define NIMG (FPT - IMG_START)        // 196

// scale * log2(e): ex2.approx(dot) == exp(dot/sqrt(32))
#define SCL2E (0.17677669529663689f * 1.4426950408889634f)

__device__ __forceinline__ u64 fma2(u64 a, u64 b, u64 c) {
    u64 d; asm("fma.rn.f32x2 %0, %1, %2, %3;" : "=l"(d) : "l"(a), "l"(b), "l"(c)); return d;
}
__device__ __forceinline__ u64 pack2(float lo, float hi) {
    u64 d; asm("mov.b64 %0, {%1, %2};" : "=l"(d) : "f"(lo), "f"(hi)); return d;
}
__device__ __forceinline__ void unpack2(u64 a, float& lo, float& hi) {
    asm("mov.b64 {%0, %1}, %2;" : "=f"(lo), "=f"(hi) : "l"(a));
}
__device__ __forceinline__ float ex2(float x) {
    float r; asm("ex2.approx.f32 %0, %1;" : "=f"(r) : "f"(x)); return r;
}

// single key step (remainder)
__device__ __forceinline__ void keyStep(const u64* __restrict__ q2, u64* __restrict__ acc,
                                        float& lsum, const float* krow, const float* vrow)
{
    const ulonglong2* k2 = (const ulonglong2*)krow;
    u64 sA = 0ull, sB = 0ull;
    ulonglong2 kk;
    kk = k2[0]; sA = fma2(q2[0],  kk.x, sA); sB = fma2(q2[1],  kk.y, sB);
    kk = k2[1]; sA = fma2(q2[2],  kk.x, sA); sB = fma2(q2[3],  kk.y, sB);
    kk = k2[2]; sA = fma2(q2[4],  kk.x, sA); sB = fma2(q2[5],  kk.y, sB);
    kk = k2[3]; sA = fma2(q2[6],  kk.x, sA); sB = fma2(q2[7],  kk.y, sB);
    kk = k2[4]; sA = fma2(q2[8],  kk.x, sA); sB = fma2(q2[9],  kk.y, sB);
    kk = k2[5]; sA = fma2(q2[10], kk.x, sA); sB = fma2(q2[11], kk.y, sB);
    kk = k2[6]; sA = fma2(q2[12], kk.x, sA); sB = fma2(q2[13], kk.y, sB);
    kk = k2[7]; sA = fma2(q2[14], kk.x, sA); sB = fma2(q2[15], kk.y, sB);
    const u64 one2 = pack2(1.0f, 1.0f);
    u64 sT = fma2(sA, one2, sB);
    float lo, hi; unpack2(sT, lo, hi);
    const float p = ex2(lo + hi);
    lsum += p;
    const u64 p2 = pack2(p, p);
    const ulonglong2* v2 = (const ulonglong2*)vrow;
    ulonglong2 vv;
    vv = v2[0]; acc[0]  = fma2(p2, vv.x, acc[0]);  acc[1]  = fma2(p2, vv.y, acc[1]);
    vv = v2[1]; acc[2]  = fma2(p2, vv.x, acc[2]);  acc[3]  = fma2(p2, vv.y, acc[3]);
    vv = v2[2]; acc[4]  = fma2(p2, vv.x, acc[4]);  acc[5]  = fma2(p2, vv.y, acc[5]);
    vv = v2[3]; acc[6]  = fma2(p2, vv.x, acc[6]);  acc[7]  = fma2(p2, vv.y, acc[7]);
    vv = v2[4]; acc[8]  = fma2(p2, vv.x, acc[8]);  acc[9]  = fma2(p2, vv.y, acc[9]);
    vv = v2[5]; acc[10] = fma2(p2, vv.x, acc[10]); acc[11] = fma2(p2, vv.y, acc[11]);
    vv = v2[6]; acc[12] = fma2(p2, vv.x, acc[12]); acc[13] = fma2(p2, vv.y, acc[13]);
    vv = v2[7]; acc[14] = fma2(p2, vv.x, acc[14]); acc[15] = fma2(p2, vv.y, acc[15]);
}

// 2-key software-pipelined step: two independent dot chains + two ex2 in flight
__device__ __forceinline__ void keyStep2(const u64* __restrict__ q2, u64* __restrict__ acc,
                                         float& lsum,
                                         const float* k0, const float* v0,
                                         const float* k1, const float* v1)
{
    const ulonglong2* ka = (const ulonglong2*)k0;
    const ulonglong2* kb = (const ulonglong2*)k1;
    u64 s0a = 0ull, s0b = 0ull, s1a = 0ull, s1b = 0ull;
    ulonglong2 x, y;
    x = ka[0]; y = kb[0]; s0a = fma2(q2[0],  x.x, s0a); s0b = fma2(q2[1],  x.y, s0b);
                          s1a = fma2(q2[0],  y.x, s1a); s1b = fma2(q2[1],  y.y, s1b);
    x = ka[1]; y = kb[1]; s0a = fma2(q2[2],  x.x, s0a); s0b = fma2(q2[3],  x.y, s0b);
                          s1a = fma2(q2[2],  y.x, s1a); s1b = fma2(q2[3],  y.y, s1b);
    x = ka[2]; y = kb[2]; s0a = fma2(q2[4],  x.x, s0a); s0b = fma2(q2[5],  x.y, s0b);
                          s1a = fma2(q2[4],  y.x, s1a); s1b = fma2(q2[5],  y.y, s1b);
    x = ka[3]; y = kb[3]; s0a = fma2(q2[6],  x.x, s0a); s0b = fma2(q2[7],  x.y, s0b);
                          s1a = fma2(q2[6],  y.x, s1a); s1b = fma2(q2[7],  y.y, s1b);
    x = ka[4]; y = kb[4]; s0a = fma2(q2[8],  x.x, s0a); s0b = fma2(q2[9],  x.y, s0b);
                          s1a = fma2(q2[8],  y.x, s1a); s1b = fma2(q2[9],  y.y, s1b);
    x = ka[5]; y = kb[5]; s0a = fma2(q2[10], x.x, s0a); s0b = fma2(q2[11], x.y, s0b);
                          s1a = fma2(q2[10], y.x, s1a); s1b = fma2(q2[11], y.y, s1b);
    x = ka[6]; y = kb[6]; s0a = fma2(q2[12], x.x, s0a); s0b = fma2(q2[13], x.y, s0b);
                          s1a = fma2(q2[12], y.x, s1a); s1b = fma2(q2[13], y.y, s1b);
    x = ka[7]; y = kb[7]; s0a = fma2(q2[14], x.x, s0a); s0b = fma2(q2[15], x.y, s0b);
                          s1a = fma2(q2[14], y.x, s1a); s1b = fma2(q2[15], y.y, s1b);
    const u64 one2 = pack2(1.0f, 1.0f);
    u64 s0 = fma2(s0a, one2, s0b);
    u64 s1 = fma2(s1a, one2, s1b);
    float l0, h0, l1, h1;
    unpack2(s0, l0, h0);
    unpack2(s1, l1, h1);
    const float p0 = ex2(l0 + h0);
    const float p1 = ex2(l1 + h1);
    lsum += p0 + p1;
    const u64 p02 = pack2(p0, p0);
    const u64 p12 = pack2(p1, p1);
    const ulonglong2* va = (const ulonglong2*)v0;
    const ulonglong2* vb = (const ulonglong2*)v1;
    #pragma unroll
    for (int i = 0; i < 8; i++) {
        ulonglong2 a = va[i];
        ulonglong2 b2 = vb[i];
        acc[2 * i]     = fma2(p02, a.x, acc[2 * i]);
        acc[2 * i + 1] = fma2(p02, a.y, acc[2 * i + 1]);
        acc[2 * i]     = fma2(p12, b2.x, acc[2 * i]);
        acc[2 * i + 1] = fma2(p12, b2.y, acc[2 * i + 1]);
    }
}

__device__ __forceinline__ void loadQ(const float* qrowp, u64* q2)
{
    const float4* qg4 = (const float4*)qrowp;
    #pragma unroll
    for (int i = 0; i < 8; i++) {
        float4 x = qg4[i];
        q2[2 * i]     = pack2(x.x * SCL2E, x.y * SCL2E);
        q2[2 * i + 1] = pack2(x.z * SCL2E, x.w * SCL2E);
    }
}

// ============================================================================
// Kernel A: img queries 20..215 (R8 structure + 2-key pipelined loops).
// 39KB tile, 3 blocks/SM, single wave, uniform 20+npk keys per thread.
// ============================================================================
#define A_THREADS 224
#define A_SK 0
#define A_SV (IMG_START * DD)                       // 640
#define A_PK (2 * IMG_START * DD)                   // 1280
#define A_PV (2 * IMG_START * DD + MAXPAST * DD)    // 5536
#define A_SMEM_BYTES ((2 * IMG_START * DD + 2 * MAXPAST * DD) * 4)  // 39168

__global__ void __launch_bounds__(A_THREADS, 3)
eye_attn_img(const float* __restrict__ q,
             const float* __restrict__ k,
             const float* __restrict__ v,
             float* __restrict__ out)
{
    extern __shared__ float smem[];
    float* sK20 = smem + A_SK;
    float* sV20 = smem + A_SV;
    float* pK   = smem + A_PK;
    float* pV   = smem + A_PV;

    const int t = blockIdx.x, h = blockIdx.y, b = blockIdx.z;
    const int tid = threadIdx.x;
    const size_t bh_base = ((size_t)(b * HH + h)) * SS * DD;
    const float* kg = k + bh_base + (size_t)t * FPT * DD;
    const float* vg = v + bh_base + (size_t)t * FPT * DD;

    // stage same-t rows 0..19 (160 float4 each)
    {
        const float4* kg4 = (const float4*)kg;
        const float4* vg4 = (const float4*)vg;
        for (int i = tid; i < IMG_START * DD / 4; i += A_THREADS) {
            ((float4*)sK20)[i] = kg4[i];
            ((float4*)sV20)[i] = vg4[i];
        }
    }

    const int npt = (t < WIN - 1) ? t : (WIN - 1);
    const int npk = npt * NPAST;

    // stage compacted past rows (dt-major order)
    {
        const int ntask = npk * 8;
        for (int r4 = tid; r4 < ntask; r4 += A_THREADS) {
            const int r = r4 >> 3, c = r4 & 7;
            const int dt = r / NPAST + 1;
            const int i  = r - (dt - 1) * NPAST;
            const int m  = (i < 4) ? i : (i + 1);
            const size_t src = bh_base + ((size_t)(t - dt) * FPT + m) * DD;
            ((float4*)pK)[r * 8 + c] = ((const float4*)(k + src))[c];
            ((float4*)pV)[r * 8 + c] = ((const float4*)(v + src))[c];
        }
    }

    __syncthreads();

    if (tid >= NIMG) return;   // 196 active

    const int qrow = IMG_START + tid;
    u64 q2[16];
    loadQ(q + bh_base + ((size_t)t * FPT + qrow) * DD, q2);

    u64 acc[16];
    #pragma unroll
    for (int i = 0; i < 16; i++) acc[i] = 0ull;
    float lsum = 0.0f;

    // Phase A: same-t rows 0..19 = 10 pipelined pairs
    #pragma unroll 2
    for (int j = 0; j < IMG_START; j += 2)
        keyStep2(q2, acc, lsum,
                 sK20 + j * DD, sV20 + j * DD,
                 sK20 + (j + 1) * DD, sV20 + (j + 1) * DD);

    // Past rows: pipelined pairs + remainder
    {
        int r = 0;
        #pragma unroll 2
        for (; r + 1 < npk; r += 2)
            keyStep2(q2, acc, lsum,
                     pK + r * DD, pV + r * DD,
                     pK + (r + 1) * DD, pV + (r + 1) * DD);
        if (r < npk)
            keyStep(q2, acc, lsum, pK + r * DD, pV + r * DD);
    }

    const float inv = 1.0f / lsum;
    float4* og4 = (float4*)(out + bh_base + ((size_t)t * FPT + qrow) * DD);
    #pragma unroll
    for (int i = 0; i < 8; i++) {
        float a0, a1, a2, a3;
        unpack2(acc[2 * i], a0, a1);
        unpack2(acc[2 * i + 1], a2, a3);
        float4 o; o.x = a0 * inv; o.y = a1 * inv; o.z = a2 * inv; o.w = a3 * inv;
        og4[i] = o;
    }
}

// ============================================================================
// Kernel B: head queries 0..19 (BYTE-IDENTICAL to round-8 B, measured 34.2us).
// 640 threads = 20 warps = 20 queries; pitch-36 smem stage of all 349 rows;
// lanes stride keys by 32; shuffle-tree combine.
// ============================================================================
#define B_THREADS 640
#define B_PITCH 36
#define B_NROWS (FPT + MAXPAST)                     // 349
#define B_SK 0
#define B_SV (B_NROWS * B_PITCH)                    // 12564
#define B_SMEM_BYTES (2 * B_NROWS * B_PITCH * 4)    // 100512

__global__ void __launch_bounds__(B_THREADS, 1)
eye_attn_head(const float* __restrict__ q,
              const float* __restrict__ k,
              const float* __restrict__ v,
              float* __restrict__ out)
{
    extern __shared__ float smem[];
    float* sK = smem + B_SK;   // rows 0..215: same-t; rows 216..: past (joint-first)
    float* sV = smem + B_SV;

    const int t = blockIdx.x, h = blockIdx.y, b = blockIdx.z;
    const int tid = threadIdx.x;
    const size_t bh_base = ((size_t)(b * HH + h)) * SS * DD;
    const float* kg = k + bh_base + (size_t)t * FPT * DD;
    const float* vg = v + bh_base + (size_t)t * FPT * DD;

    const int npt = (t < WIN - 1) ? t : (WIN - 1);
    const int npk = npt * NPAST;
    const int n4  = npt * 4;

    // stage same-t rows 0..215 at pitch 36
    for (int i = tid; i < FPT * 8; i += B_THREADS) {
        const int r = i >> 3, c = i & 7;
        float4 kk = ((const float4*)(kg + (size_t)r * DD))[c];
        float4 vv = ((const float4*)(vg + (size_t)r * DD))[c];
        *(float4*)(sK + r * B_PITCH + c * 4) = kk;
        *(float4*)(sV + r * B_PITCH + c * 4) = vv;
    }
    // stage past rows JOINT-FIRST at rows 216..
    {
        const int ntask = npk * 8;
        for (int i = tid; i < ntask; i += B_THREADS) {
            const int r = i >> 3, c = i & 7;
            int dt, m;
            if (r < n4) { dt = (r >> 2) + 1; m = r & 3; }
            else        { const int r2 = r - n4; dt = r2 / 15 + 1; m = 5 + r2 - (dt - 1) * 15; }
            const size_t src = bh_base + ((size_t)(t - dt) * FPT + m) * DD;
            float4 kk = ((const float4*)(k + src))[c];
            float4 vv = ((const float4*)(v + src))[c];
            *(float4*)(sK + (FPT + r) * B_PITCH + c * 4) = kk;
            *(float4*)(sV + (FPT + r) * B_PITCH + c * 4) = vv;
        }
    }
    __syncthreads();

    const int wq   = tid >> 5;
    const int lane = tid & 31;
    const int Lq = FPT + ((wq < JOINT_START) ? npk : n4);

    u64 q2[16];
    loadQ(q + bh_base + ((size_t)t * FPT + wq) * DD, q2);

    u64 acc[16];
    #pragma unroll
    for (int i = 0; i < 16; i++) acc[i] = 0ull;
    float lsum = 0.0f;

    for (int idx = lane; idx < Lq; idx += 32)
        keyStep(q2, acc, lsum, sK + idx * B_PITCH, sV + idx * B_PITCH);

    const u64 one2 = pack2(1.0f, 1.0f);
    #pragma unroll
    for (int off = 16; off >= 1; off >>= 1) {
        lsum += __shfl_xor_sync(0xFFFFFFFFu, lsum, off);
        #pragma unroll
        for (int i = 0; i < 16; i++) {
            u64 other = __shfl_xor_sync(0xFFFFFFFFu, acc[i], off);
            acc[i] = fma2(other, one2, acc[i]);
        }
    }

    if (lane == 0) {
        const float inv = 1.0f / lsum;
        float4* og4 = (float4*)(out + bh_base + ((size_t)t * FPT + wq) * DD);
        #pragma unroll
        for (int i = 0; i < 8; i++) {
            float a0, a1, a2, a3;
            unpack2(acc[2 * i], a0, a1);
            unpack2(acc[2 * i + 1], a2, a3);
            float4 o; o.x = a0 * inv; o.y = a1 * inv; o.z = a2 * inv; o.w = a3 * inv;
            og4[i] = o;
        }
    }
}

extern "C" void kernel_launch(void* const* d_in, const int* in_sizes, int n_in,
                              void* d_out, int out_size)
{
    const float* q = (const float*)d_in[0];
    const float* k = (const float*)d_in[1];
    const float* v = (const float*)d_in[2];
    float* out = (float*)d_out;

    cudaFuncSetAttribute(eye_attn_img,
                         cudaFuncAttributeMaxDynamicSharedMemorySize, A_SMEM_BYTES);
    cudaFuncSetAttribute(eye_attn_head,
                         cudaFuncAttributeMaxDynamicSharedMemorySize, B_SMEM_BYTES);

    dim3 grid(NT, HH, BB);   // (16, 12, 2)
    eye_attn_img<<<grid, A_THREADS, A_SMEM_BYTES>>>(q, k, v, out);
    eye_attn_head<<<grid, B_THREADS, B_SMEM_BYTES>>>(q, k, v, out);
}